// round 1
// baseline (speedup 1.0000x reference)
#include <cuda_runtime.h>
#include <cstdint>

// ---------------- problem dims ----------------
#define NTOK 4096
#define CDIM 1024
#define ENUM 8
#define HDIM 512
#define HSDIM 2048

// ---------------- GEMM tiling ----------------
#define BM 128
#define BN 128
#define BK 32
#define AST 36     // A/Bt smem row stride (floats)
#define BST 136    // B  smem row stride (floats)
#define SMEMB ((2*(BM*AST) + 2*(BM*AST)) * 4)   // 73728 B worst case

// ---------------- device scratch (static, allowed) ----------------
__device__ int   d_cnt[ENUM];
__device__ int   d_tok[ENUM][NTOK];       // expert slot -> token id
__device__ float d_gate[ENUM][NTOK];      // expert slot -> sigmoid gate
__device__ int   d_eslot[NTOK][2];        // token -> e*NTOK+slot (two routed experts)
__device__ float d_gu  [ENUM*NTOK*1024];  // expert gate_up output   (128 MB)
__device__ float d_hid [ENUM*NTOK*HDIM];  // expert hidden           ( 64 MB)
__device__ float d_pair[ENUM*NTOK*CDIM];  // gate-scaled expert out  (128 MB)
__device__ float d_sg  [NTOK*HSDIM];
__device__ float d_su  [NTOK*HSDIM];
__device__ float d_sh  [NTOK*HSDIM];

// ---------------- helpers ----------------
__device__ __forceinline__ uint32_t f2tf(float f) {
    uint32_t u; asm("cvt.rna.tf32.f32 %0, %1;" : "=r"(u) : "f"(f)); return u;
}
__device__ __forceinline__ void cp16(float* s, const float* g) {
    uint32_t sa = (uint32_t)__cvta_generic_to_shared(s);
    asm volatile("cp.async.cg.shared.global [%0], [%1], 16;" :: "r"(sa), "l"(g));
}
__device__ __forceinline__ void mma8(float* d, const uint32_t* a, const uint32_t* b) {
    asm volatile(
        "mma.sync.aligned.m16n8k8.row.col.f32.tf32.tf32.f32 "
        "{%0,%1,%2,%3},{%4,%5,%6,%7},{%8,%9},{%0,%1,%2,%3};"
        : "+f"(d[0]), "+f"(d[1]), "+f"(d[2]), "+f"(d[3])
        : "r"(a[0]), "r"(a[1]), "r"(a[2]), "r"(a[3]), "r"(b[0]), "r"(b[1]));
}

// ---------------- router: logits, top-2, sigmoid gates, expert lists ----------------
__global__ void router_kernel(const float* __restrict__ x, const float* __restrict__ rw) {
    int t = blockIdx.x * (blockDim.x >> 5) + (threadIdx.x >> 5);
    int lane = threadIdx.x & 31;
    if (t >= NTOK) return;
    const float* xr = x + (long long)t * CDIM;
    float acc[ENUM];
#pragma unroll
    for (int e = 0; e < ENUM; e++) acc[e] = 0.f;
    for (int i = lane; i < CDIM; i += 32) {
        float xv = xr[i];
#pragma unroll
        for (int e = 0; e < ENUM; e++) acc[e] += xv * rw[e * CDIM + i];
    }
#pragma unroll
    for (int e = 0; e < ENUM; e++)
#pragma unroll
        for (int off = 16; off; off >>= 1) acc[e] += __shfl_xor_sync(~0u, acc[e], off);
    if (lane == 0) {
        int i0 = 0; float v0 = acc[0];
#pragma unroll
        for (int e = 1; e < ENUM; e++) if (acc[e] > v0) { v0 = acc[e]; i0 = e; }
        int i1 = -1; float v1 = -3.0e38f;
#pragma unroll
        for (int e = 0; e < ENUM; e++) if (e != i0 && acc[e] > v1) { v1 = acc[e]; i1 = e; }
        float g0 = 1.f / (1.f + expf(-v0));
        float g1 = 1.f / (1.f + expf(-v1));
        int s0 = atomicAdd(&d_cnt[i0], 1);
        int s1 = atomicAdd(&d_cnt[i1], 1);
        d_tok[i0][s0] = t; d_gate[i0][s0] = g0; d_eslot[t][0] = i0 * NTOK + s0;
        d_tok[i1][s1] = t; d_gate[i1][s1] = g1; d_eslot[t][1] = i1 * NTOK + s1;
    }
}

// ---------------- TF32 tensor-core GEMM ----------------
// C[M,N] (+epilogue) = A[M,K] * B[K,N]
// GATHER: A rows indirected through d_tok[z]
// BT:     B stored as [N,K] row-major (transposed weights)
// EPI: 0 = plain store, 1 = scale rows by d_gate[z][row] (expert down-proj)
template <bool GATHER, bool BT, int EPI>
__global__ __launch_bounds__(256, 1) void gemm_tf32(
    const float* __restrict__ Abase, long long aZ, int lda,
    const float* __restrict__ Bbase, long long bZ, int ldb,
    float* __restrict__ Cbase, long long cZ, int ldc,
    int K, int M /* -1 => use d_cnt[z] */)
{
    const int z  = blockIdx.z;
    const int bm = blockIdx.y, bn = blockIdx.x;
    if (M < 0 && bm * BM >= d_cnt[z]) return;

    const float* A = Abase + (long long)z * aZ;
    const float* B = Bbase + (long long)z * bZ;
    float*       Cp = Cbase + (long long)z * cZ;

    extern __shared__ __align__(16) float smem[];
    float* sA = smem;                           // [2][BM][AST]
    float* sB = smem + 2 * BM * AST;            // BT ? [2][BN][AST] : [2][BK][BST]
    const int sBsz = BT ? BN * AST : BK * BST;

    const int tid = threadIdx.x, lane = tid & 31, w = tid >> 5;
    const int wm = w >> 2, wn = w & 3;          // 2 x 4 warp grid, each 64x32

    auto loadA = [&](int stage, int k0) {
        float* dst = sA + stage * BM * AST;
#pragma unroll
        for (int c = 0; c < 4; c++) {
            int id  = c * 256 + tid;
            int row = id >> 3, kc = (id & 7) * 4;
            int grow = bm * BM + row;
            int arow = GATHER ? d_tok[z][grow] : grow;
            cp16(dst + row * AST + kc, A + (long long)arow * lda + k0 + kc);
        }
    };
    auto loadB = [&](int stage, int k0) {
        float* dst = sB + stage * sBsz;
#pragma unroll
        for (int c = 0; c < 4; c++) {
            int id = c * 256 + tid;
            if (BT) {
                int nr = id >> 3, kc = (id & 7) * 4;
                cp16(dst + nr * AST + kc, B + (long long)(bn * BN + nr) * ldb + k0 + kc);
            } else {
                int kr = id >> 5, nc = (id & 31) * 4;
                cp16(dst + kr * BST + nc, B + (long long)(k0 + kr) * ldb + bn * BN + nc);
            }
        }
    };

    float acc[4][4][4];
#pragma unroll
    for (int im = 0; im < 4; im++)
#pragma unroll
        for (int in = 0; in < 4; in++)
#pragma unroll
            for (int q = 0; q < 4; q++) acc[im][in][q] = 0.f;

    const int nk = K / BK;
    loadA(0, 0); loadB(0, 0);
    asm volatile("cp.async.commit_group;");

    for (int kt = 0; kt < nk; kt++) {
        asm volatile("cp.async.wait_group 0;");
        __syncthreads();
        if (kt + 1 < nk) {
            loadA((kt + 1) & 1, (kt + 1) * BK);
            loadB((kt + 1) & 1, (kt + 1) * BK);
            asm volatile("cp.async.commit_group;");
        }
        const float* cA = sA + (kt & 1) * BM * AST;
        const float* cB = sB + (kt & 1) * sBsz;

#pragma unroll
        for (int ks = 0; ks < 4; ks++) {
            const int kb = ks * 8;
            uint32_t af[4][4], bf[4][2];
#pragma unroll
            for (int im = 0; im < 4; im++) {
                int r = wm * 64 + im * 16;
                af[im][0] = f2tf(cA[(r     + (lane >> 2)) * AST + kb     + (lane & 3)]);
                af[im][1] = f2tf(cA[(r + 8 + (lane >> 2)) * AST + kb     + (lane & 3)]);
                af[im][2] = f2tf(cA[(r     + (lane >> 2)) * AST + kb + 4 + (lane & 3)]);
                af[im][3] = f2tf(cA[(r + 8 + (lane >> 2)) * AST + kb + 4 + (lane & 3)]);
            }
#pragma unroll
            for (int in = 0; in < 4; in++) {
                int cn = wn * 32 + in * 8 + (lane >> 2);
                if (BT) {
                    bf[in][0] = f2tf(cB[cn * AST + kb     + (lane & 3)]);
                    bf[in][1] = f2tf(cB[cn * AST + kb + 4 + (lane & 3)]);
                } else {
                    bf[in][0] = f2tf(cB[(kb     + (lane & 3)) * BST + cn]);
                    bf[in][1] = f2tf(cB[(kb + 4 + (lane & 3)) * BST + cn]);
                }
            }
#pragma unroll
            for (int im = 0; im < 4; im++)
#pragma unroll
                for (int in = 0; in < 4; in++)
                    mma8(acc[im][in], af[im], bf[in]);
        }
        __syncthreads();
    }

    // epilogue
#pragma unroll
    for (int im = 0; im < 4; im++) {
        int r0 = bm * BM + wm * 64 + im * 16 + (lane >> 2);
        float s0 = 1.f, s1 = 1.f;
        if (EPI == 1) { s0 = d_gate[z][r0]; s1 = d_gate[z][r0 + 8]; }
#pragma unroll
        for (int in = 0; in < 4; in++) {
            int c0 = bn * BN + wn * 32 + in * 8 + (lane & 3) * 2;
            Cp[(long long)r0 * ldc + c0]           = acc[im][in][0] * s0;
            Cp[(long long)r0 * ldc + c0 + 1]       = acc[im][in][1] * s0;
            Cp[(long long)(r0 + 8) * ldc + c0]     = acc[im][in][2] * s1;
            Cp[(long long)(r0 + 8) * ldc + c0 + 1] = acc[im][in][3] * s1;
        }
    }
}

// ---------------- elementwise SwiGLU kernels ----------------
__device__ __forceinline__ float silu_f(float v) { return v / (1.f + expf(-v)); }

__global__ void silu_mul_experts() {
    int mt = blockIdx.x, e = blockIdx.y;
    if (mt * 128 >= d_cnt[e]) return;
    const float4* gu = (const float4*)(d_gu + ((long long)e * NTOK + mt * 128) * 1024);
    float4* hid = (float4*)(d_hid + ((long long)e * NTOK + mt * 128) * HDIM);
    for (int i = threadIdx.x; i < 128 * 128; i += 256) {
        int row = i >> 7, j = i & 127;
        float4 g = gu[row * 256 + j];
        float4 u = gu[row * 256 + 128 + j];
        float4 h;
        h.x = silu_f(g.x) * u.x; h.y = silu_f(g.y) * u.y;
        h.z = silu_f(g.z) * u.z; h.w = silu_f(g.w) * u.w;
        hid[row * 128 + j] = h;
    }
}

__global__ void silu_mul_shared() {
    long long i = (long long)blockIdx.x * 256 + threadIdx.x;
    float4 g = ((const float4*)d_sg)[i];
    float4 u = ((const float4*)d_su)[i];
    float4 h;
    h.x = silu_f(g.x) * u.x; h.y = silu_f(g.y) * u.y;
    h.z = silu_f(g.z) * u.z; h.w = silu_f(g.w) * u.w;
    ((float4*)d_sh)[i] = h;
}

// ---------------- final combine: out = shared + gated expert pair ----------------
__global__ void combine_kernel(float* __restrict__ out) {
    long long i = (long long)blockIdx.x * 256 + threadIdx.x;   // over 4096*256 float4
    int t = (int)(i >> 8), j = (int)(i & 255);
    int es0 = d_eslot[t][0], es1 = d_eslot[t][1];
    float4 o  = ((float4*)out)[i];
    float4 p0 = ((const float4*)d_pair)[(long long)es0 * 256 + j];
    float4 p1 = ((const float4*)d_pair)[(long long)es1 * 256 + j];
    o.x += p0.x + p1.x; o.y += p0.y + p1.y;
    o.z += p0.z + p1.z; o.w += p0.w + p1.w;
    ((float4*)out)[i] = o;
}

// ---------------- launch ----------------
extern "C" void kernel_launch(void* const* d_in, const int* in_sizes, int n_in,
                              void* d_out, int out_size) {
    const float* x   = (const float*)d_in[0];
    const float* rw  = (const float*)d_in[1];
    const float* guw = (const float*)d_in[2];
    const float* dw  = (const float*)d_in[3];
    const float* sgw = (const float*)d_in[4];
    const float* suw = (const float*)d_in[5];
    const float* sdw = (const float*)d_in[6];
    float* out = (float*)d_out;

    float *p_gu, *p_hid, *p_pair, *p_sg, *p_su, *p_sh;
    void* addr;
    cudaGetSymbolAddress(&addr, d_gu);   p_gu   = (float*)addr;
    cudaGetSymbolAddress(&addr, d_hid);  p_hid  = (float*)addr;
    cudaGetSymbolAddress(&addr, d_pair); p_pair = (float*)addr;
    cudaGetSymbolAddress(&addr, d_sg);   p_sg   = (float*)addr;
    cudaGetSymbolAddress(&addr, d_su);   p_su   = (float*)addr;
    cudaGetSymbolAddress(&addr, d_sh);   p_sh   = (float*)addr;

    void* cntAddr; cudaGetSymbolAddress(&cntAddr, d_cnt);
    cudaMemsetAsync(cntAddr, 0, sizeof(int) * ENUM);

    cudaFuncSetAttribute(gemm_tf32<true,  false, 0>, cudaFuncAttributeMaxDynamicSharedMemorySize, SMEMB);
    cudaFuncSetAttribute(gemm_tf32<false, false, 1>, cudaFuncAttributeMaxDynamicSharedMemorySize, SMEMB);
    cudaFuncSetAttribute(gemm_tf32<false, true,  0>, cudaFuncAttributeMaxDynamicSharedMemorySize, SMEMB);

    // 1) router
    router_kernel<<<NTOK / 8, 256>>>(x, rw);

    // 2) expert gate_up:  gu[e,slot,:] = x[tok] @ gate_up_w[e]   (M=cnt[e], N=1024, K=1024)
    gemm_tf32<true, false, 0><<<dim3(8, 32, 8), 256, SMEMB>>>(
        x, 0, CDIM,
        guw, (long long)CDIM * 1024, 1024,
        p_gu, (long long)NTOK * 1024, 1024,
        CDIM, -1);

    // 3) hidden = silu(gate)*up
    silu_mul_experts<<<dim3(32, 8), 256>>>();

    // 4) expert down, gate-scaled:  pair[e,slot,:] = gate * (hidden @ down_w[e])
    gemm_tf32<false, false, 1><<<dim3(8, 32, 8), 256, SMEMB>>>(
        p_hid, (long long)NTOK * HDIM, HDIM,
        dw, (long long)HDIM * CDIM, CDIM,
        p_pair, (long long)NTOK * CDIM, CDIM,
        HDIM, -1);

    // 5) shared gate / up:  [4096,1024] x [1024,2048] (B transposed: W is [HS,C])
    gemm_tf32<false, true, 0><<<dim3(16, 32, 1), 256, SMEMB>>>(
        x, 0, CDIM, sgw, 0, CDIM, p_sg, 0, HSDIM, CDIM, NTOK);
    gemm_tf32<false, true, 0><<<dim3(16, 32, 1), 256, SMEMB>>>(
        x, 0, CDIM, suw, 0, CDIM, p_su, 0, HSDIM, CDIM, NTOK);

    // 6) shared SwiGLU elementwise
    silu_mul_shared<<<(NTOK * HSDIM / 4) / 256, 256>>>();

    // 7) shared down -> writes base of output:  [4096,2048] x [2048,1024] (B transposed)
    gemm_tf32<false, true, 0><<<dim3(8, 32, 1), 256, SMEMB>>>(
        p_sh, 0, HSDIM, sdw, 0, HSDIM, out, 0, CDIM, HSDIM, NTOK);

    // 8) out += gated expert pair
    combine_kernel<<<NTOK, 256>>>(out);

    (void)in_sizes; (void)n_in; (void)out_size;
}

// round 2
// speedup vs baseline: 1.1131x; 1.1131x over previous
#include <cuda_runtime.h>
#include <cstdint>

// ---------------- problem dims ----------------
#define NTOK 4096
#define CDIM 1024
#define ENUM 8
#define HDIM 512
#define HSDIM 2048

// ---------------- GEMM tiling ----------------
#define BM 128
#define BN 128
#define BK 32
#define AST 36     // A/Bt smem row stride (floats)
#define BST 136    // B  smem row stride (floats)
#define NSTAGE 3
#define SA_STAGE (BM * AST)          // 4608 floats
#define SB_STAGE_NB (BK * BST)       // 4352 floats
#define SB_STAGE_BT (BN * AST)       // 4608 floats
#define SMEMB_NB ((NSTAGE * SA_STAGE + NSTAGE * SB_STAGE_NB) * 4)   // 107520 B
#define SMEMB_BT ((NSTAGE * SA_STAGE + NSTAGE * SB_STAGE_BT) * 4)   // 110592 B

// ---------------- device scratch (static, allowed) ----------------
__device__ int   d_cnt[ENUM];
__device__ int   d_tok[ENUM][NTOK];       // expert slot -> token id
__device__ float d_gate[ENUM][NTOK];      // expert slot -> sigmoid gate
__device__ int   d_eslot[NTOK][2];        // token -> e*NTOK+slot (two routed experts)
__device__ float d_gu  [ENUM*NTOK*1024];  // expert gate_up output   (128 MB)
__device__ float d_hid [ENUM*NTOK*HDIM];  // expert hidden           ( 64 MB)
__device__ float d_pair[ENUM*NTOK*CDIM];  // gate-scaled expert out  (128 MB)
__device__ float d_sg  [NTOK*HSDIM];
__device__ float d_su  [NTOK*HSDIM];
__device__ float d_sh  [NTOK*HSDIM];

// ---------------- helpers ----------------
__device__ __forceinline__ uint32_t f2tf(float f) {
    uint32_t u; asm("cvt.rna.tf32.f32 %0, %1;" : "=r"(u) : "f"(f)); return u;
}
__device__ __forceinline__ void cp16(float* s, const float* g) {
    uint32_t sa = (uint32_t)__cvta_generic_to_shared(s);
    asm volatile("cp.async.cg.shared.global [%0], [%1], 16;" :: "r"(sa), "l"(g));
}
__device__ __forceinline__ void mma8(float* d, const uint32_t* a, const uint32_t* b) {
    asm volatile(
        "mma.sync.aligned.m16n8k8.row.col.f32.tf32.tf32.f32 "
        "{%0,%1,%2,%3},{%4,%5,%6,%7},{%8,%9},{%0,%1,%2,%3};"
        : "+f"(d[0]), "+f"(d[1]), "+f"(d[2]), "+f"(d[3])
        : "r"(a[0]), "r"(a[1]), "r"(a[2]), "r"(a[3]), "r"(b[0]), "r"(b[1]));
}

// ---------------- router: logits, top-2, sigmoid gates, expert lists ----------------
__global__ void router_kernel(const float* __restrict__ x, const float* __restrict__ rw) {
    int t = blockIdx.x * (blockDim.x >> 5) + (threadIdx.x >> 5);
    int lane = threadIdx.x & 31;
    if (t >= NTOK) return;
    const float* xr = x + (long long)t * CDIM;
    float acc[ENUM];
#pragma unroll
    for (int e = 0; e < ENUM; e++) acc[e] = 0.f;
    for (int i = lane; i < CDIM; i += 32) {
        float xv = xr[i];
#pragma unroll
        for (int e = 0; e < ENUM; e++) acc[e] += xv * rw[e * CDIM + i];
    }
#pragma unroll
    for (int e = 0; e < ENUM; e++)
#pragma unroll
        for (int off = 16; off; off >>= 1) acc[e] += __shfl_xor_sync(~0u, acc[e], off);
    if (lane == 0) {
        int i0 = 0; float v0 = acc[0];
#pragma unroll
        for (int e = 1; e < ENUM; e++) if (acc[e] > v0) { v0 = acc[e]; i0 = e; }
        int i1 = -1; float v1 = -3.0e38f;
#pragma unroll
        for (int e = 0; e < ENUM; e++) if (e != i0 && acc[e] > v1) { v1 = acc[e]; i1 = e; }
        float g0 = 1.f / (1.f + expf(-v0));
        float g1 = 1.f / (1.f + expf(-v1));
        int s0 = atomicAdd(&d_cnt[i0], 1);
        int s1 = atomicAdd(&d_cnt[i1], 1);
        d_tok[i0][s0] = t; d_gate[i0][s0] = g0; d_eslot[t][0] = i0 * NTOK + s0;
        d_tok[i1][s1] = t; d_gate[i1][s1] = g1; d_eslot[t][1] = i1 * NTOK + s1;
    }
}

// ---------------- TF32 tensor-core GEMM (3-stage pipeline, 2 CTA/SM) ----------------
// C[M,N] (+epilogue) = A[M,K] * B[K,N]
// GATHER: A rows indirected through d_tok[z]
// BT:     B stored as [N,K] row-major (transposed weights)
// EPI: 0 = plain store, 1 = scale rows by d_gate[z][row] (expert down-proj)
template <bool GATHER, bool BT, int EPI>
__global__ __launch_bounds__(256, 2) void gemm_tf32(
    const float* __restrict__ Abase, long long aZ, int lda,
    const float* __restrict__ Bbase, long long bZ, int ldb,
    float* __restrict__ Cbase, long long cZ, int ldc,
    int K, int M /* -1 => use d_cnt[z] */)
{
    const int z  = blockIdx.z;
    const int bm = blockIdx.y, bn = blockIdx.x;
    if (M < 0 && bm * BM >= d_cnt[z]) return;

    const float* A = Abase + (long long)z * aZ;
    const float* B = Bbase + (long long)z * bZ;
    float*       Cp = Cbase + (long long)z * cZ;

    extern __shared__ __align__(16) float smem[];
    float* sA = smem;                                 // [NSTAGE][BM][AST]
    float* sB = smem + NSTAGE * SA_STAGE;             // BT ? [NSTAGE][BN][AST] : [NSTAGE][BK][BST]
    const int sBsz = BT ? SB_STAGE_BT : SB_STAGE_NB;

    const int tid = threadIdx.x, lane = tid & 31, w = tid >> 5;
    const int wm = w >> 2, wn = w & 3;                // 2 x 4 warp grid, each 64x32

    auto loadA = [&](int stage, int k0) {
        float* dst = sA + stage * SA_STAGE;
#pragma unroll
        for (int c = 0; c < 4; c++) {
            int id  = c * 256 + tid;
            int row = id >> 3, kc = (id & 7) * 4;
            int grow = bm * BM + row;
            int arow = GATHER ? d_tok[z][grow] : grow;
            cp16(dst + row * AST + kc, A + (long long)arow * lda + k0 + kc);
        }
    };
    auto loadB = [&](int stage, int k0) {
        float* dst = sB + stage * sBsz;
#pragma unroll
        for (int c = 0; c < 4; c++) {
            int id = c * 256 + tid;
            if (BT) {
                int nr = id >> 3, kc = (id & 7) * 4;
                cp16(dst + nr * AST + kc, B + (long long)(bn * BN + nr) * ldb + k0 + kc);
            } else {
                int kr = id >> 5, nc = (id & 31) * 4;
                cp16(dst + kr * BST + nc, B + (long long)(k0 + kr) * ldb + bn * BN + nc);
            }
        }
    };

    float acc[4][4][4];
#pragma unroll
    for (int im = 0; im < 4; im++)
#pragma unroll
        for (int in = 0; in < 4; in++)
#pragma unroll
            for (int q = 0; q < 4; q++) acc[im][in][q] = 0.f;

    const int nk = K / BK;
    loadA(0, 0); loadB(0, 0);
    asm volatile("cp.async.commit_group;");
    loadA(1, BK); loadB(1, BK);
    asm volatile("cp.async.commit_group;");

    for (int kt = 0; kt < nk; kt++) {
        if (kt + 1 < nk) { asm volatile("cp.async.wait_group 1;"); }
        else             { asm volatile("cp.async.wait_group 0;"); }
        __syncthreads();   // stage kt visible to all; all warps done with stage kt-1's buffer reuse target

        if (kt + 2 < nk) {
            int st = (kt + 2) % NSTAGE;
            loadA(st, (kt + 2) * BK);
            loadB(st, (kt + 2) * BK);
            asm volatile("cp.async.commit_group;");
        }

        const float* cA = sA + (kt % NSTAGE) * SA_STAGE;
        const float* cB = sB + (kt % NSTAGE) * sBsz;

#pragma unroll
        for (int ks = 0; ks < 4; ks++) {
            const int kb = ks * 8;
            uint32_t af[4][4], bf[4][2];
#pragma unroll
            for (int im = 0; im < 4; im++) {
                int r = wm * 64 + im * 16;
                af[im][0] = f2tf(cA[(r     + (lane >> 2)) * AST + kb     + (lane & 3)]);
                af[im][1] = f2tf(cA[(r + 8 + (lane >> 2)) * AST + kb     + (lane & 3)]);
                af[im][2] = f2tf(cA[(r     + (lane >> 2)) * AST + kb + 4 + (lane & 3)]);
                af[im][3] = f2tf(cA[(r + 8 + (lane >> 2)) * AST + kb + 4 + (lane & 3)]);
            }
#pragma unroll
            for (int in = 0; in < 4; in++) {
                int cn = wn * 32 + in * 8 + (lane >> 2);
                if (BT) {
                    bf[in][0] = f2tf(cB[cn * AST + kb     + (lane & 3)]);
                    bf[in][1] = f2tf(cB[cn * AST + kb + 4 + (lane & 3)]);
                } else {
                    bf[in][0] = f2tf(cB[(kb     + (lane & 3)) * BST + cn]);
                    bf[in][1] = f2tf(cB[(kb + 4 + (lane & 3)) * BST + cn]);
                }
            }
#pragma unroll
            for (int im = 0; im < 4; im++)
#pragma unroll
                for (int in = 0; in < 4; in++)
                    mma8(acc[im][in], af[im], bf[in]);
        }
    }

    // epilogue
#pragma unroll
    for (int im = 0; im < 4; im++) {
        int r0 = bm * BM + wm * 64 + im * 16 + (lane >> 2);
        float s0 = 1.f, s1 = 1.f;
        if (EPI == 1) { s0 = d_gate[z][r0]; s1 = d_gate[z][r0 + 8]; }
#pragma unroll
        for (int in = 0; in < 4; in++) {
            int c0 = bn * BN + wn * 32 + in * 8 + (lane & 3) * 2;
            Cp[(long long)r0 * ldc + c0]           = acc[im][in][0] * s0;
            Cp[(long long)r0 * ldc + c0 + 1]       = acc[im][in][1] * s0;
            Cp[(long long)(r0 + 8) * ldc + c0]     = acc[im][in][2] * s1;
            Cp[(long long)(r0 + 8) * ldc + c0 + 1] = acc[im][in][3] * s1;
        }
    }
}

// ---------------- elementwise SwiGLU kernels ----------------
__device__ __forceinline__ float silu_f(float v) { return v / (1.f + expf(-v)); }

__global__ void silu_mul_experts() {
    int mt = blockIdx.x, e = blockIdx.y;
    if (mt * 128 >= d_cnt[e]) return;
    const float4* gu = (const float4*)(d_gu + ((long long)e * NTOK + mt * 128) * 1024);
    float4* hid = (float4*)(d_hid + ((long long)e * NTOK + mt * 128) * HDIM);
    for (int i = threadIdx.x; i < 128 * 128; i += 256) {
        int row = i >> 7, j = i & 127;
        float4 g = gu[row * 256 + j];
        float4 u = gu[row * 256 + 128 + j];
        float4 h;
        h.x = silu_f(g.x) * u.x; h.y = silu_f(g.y) * u.y;
        h.z = silu_f(g.z) * u.z; h.w = silu_f(g.w) * u.w;
        hid[row * 128 + j] = h;
    }
}

__global__ void silu_mul_shared() {
    long long i = (long long)blockIdx.x * 256 + threadIdx.x;
    float4 g = ((const float4*)d_sg)[i];
    float4 u = ((const float4*)d_su)[i];
    float4 h;
    h.x = silu_f(g.x) * u.x; h.y = silu_f(g.y) * u.y;
    h.z = silu_f(g.z) * u.z; h.w = silu_f(g.w) * u.w;
    ((float4*)d_sh)[i] = h;
}

// ---------------- final combine: out = shared + gated expert pair ----------------
__global__ void combine_kernel(float* __restrict__ out) {
    long long i = (long long)blockIdx.x * 256 + threadIdx.x;   // over 4096*256 float4
    int t = (int)(i >> 8), j = (int)(i & 255);
    int es0 = d_eslot[t][0], es1 = d_eslot[t][1];
    float4 o  = ((float4*)out)[i];
    float4 p0 = ((const float4*)d_pair)[(long long)es0 * 256 + j];
    float4 p1 = ((const float4*)d_pair)[(long long)es1 * 256 + j];
    o.x += p0.x + p1.x; o.y += p0.y + p1.y;
    o.z += p0.z + p1.z; o.w += p0.w + p1.w;
    ((float4*)out)[i] = o;
}

// ---------------- launch ----------------
extern "C" void kernel_launch(void* const* d_in, const int* in_sizes, int n_in,
                              void* d_out, int out_size) {
    const float* x   = (const float*)d_in[0];
    const float* rw  = (const float*)d_in[1];
    const float* guw = (const float*)d_in[2];
    const float* dw  = (const float*)d_in[3];
    const float* sgw = (const float*)d_in[4];
    const float* suw = (const float*)d_in[5];
    const float* sdw = (const float*)d_in[6];
    float* out = (float*)d_out;

    float *p_gu, *p_hid, *p_pair, *p_sg, *p_su, *p_sh;
    void* addr;
    cudaGetSymbolAddress(&addr, d_gu);   p_gu   = (float*)addr;
    cudaGetSymbolAddress(&addr, d_hid);  p_hid  = (float*)addr;
    cudaGetSymbolAddress(&addr, d_pair); p_pair = (float*)addr;
    cudaGetSymbolAddress(&addr, d_sg);   p_sg   = (float*)addr;
    cudaGetSymbolAddress(&addr, d_su);   p_su   = (float*)addr;
    cudaGetSymbolAddress(&addr, d_sh);   p_sh   = (float*)addr;

    void* cntAddr; cudaGetSymbolAddress(&cntAddr, d_cnt);
    cudaMemsetAsync(cntAddr, 0, sizeof(int) * ENUM);

    cudaFuncSetAttribute(gemm_tf32<true,  false, 0>, cudaFuncAttributeMaxDynamicSharedMemorySize, SMEMB_NB);
    cudaFuncSetAttribute(gemm_tf32<false, false, 1>, cudaFuncAttributeMaxDynamicSharedMemorySize, SMEMB_NB);
    cudaFuncSetAttribute(gemm_tf32<false, true,  0>, cudaFuncAttributeMaxDynamicSharedMemorySize, SMEMB_BT);

    // 1) router
    router_kernel<<<NTOK / 8, 256>>>(x, rw);

    // 2) expert gate_up:  gu[e,slot,:] = x[tok] @ gate_up_w[e]   (M=cnt[e], N=1024, K=1024)
    gemm_tf32<true, false, 0><<<dim3(8, 32, 8), 256, SMEMB_NB>>>(
        x, 0, CDIM,
        guw, (long long)CDIM * 1024, 1024,
        p_gu, (long long)NTOK * 1024, 1024,
        CDIM, -1);

    // 3) hidden = silu(gate)*up
    silu_mul_experts<<<dim3(32, 8), 256>>>();

    // 4) expert down, gate-scaled:  pair[e,slot,:] = gate * (hidden @ down_w[e])
    gemm_tf32<false, false, 1><<<dim3(8, 32, 8), 256, SMEMB_NB>>>(
        p_hid, (long long)NTOK * HDIM, HDIM,
        dw, (long long)HDIM * CDIM, CDIM,
        p_pair, (long long)NTOK * CDIM, CDIM,
        HDIM, -1);

    // 5) shared gate / up:  [4096,1024] x [1024,2048] (B transposed: W is [HS,C])
    gemm_tf32<false, true, 0><<<dim3(16, 32, 1), 256, SMEMB_BT>>>(
        x, 0, CDIM, sgw, 0, CDIM, p_sg, 0, HSDIM, CDIM, NTOK);
    gemm_tf32<false, true, 0><<<dim3(16, 32, 1), 256, SMEMB_BT>>>(
        x, 0, CDIM, suw, 0, CDIM, p_su, 0, HSDIM, CDIM, NTOK);

    // 6) shared SwiGLU elementwise
    silu_mul_shared<<<(NTOK * HSDIM / 4) / 256, 256>>>();

    // 7) shared down -> writes base of output:  [4096,2048] x [2048,1024] (B transposed)
    gemm_tf32<false, true, 0><<<dim3(8, 32, 1), 256, SMEMB_BT>>>(
        p_sh, 0, HSDIM, sdw, 0, HSDIM, out, 0, CDIM, HSDIM, NTOK);

    // 8) out += gated expert pair
    combine_kernel<<<NTOK, 256>>>(out);

    (void)in_sizes; (void)n_in; (void)out_size;
}

// round 4
// speedup vs baseline: 1.3451x; 1.2084x over previous
#include <cuda_runtime.h>
#include <cstdint>

// ---------------- problem dims ----------------
#define NTOK 4096
#define CDIM 1024
#define ENUM 8
#define HDIM 512
#define HSDIM 2048

// ---------------- GEMM tiling ----------------
#define BM 128
#define BK 32
#define AST 36                       // smem row stride (floats)
#define NSTAGE 3
#define STG (BM * AST)               // 4608 floats per stage (A and B both 128 rows)
#define SMEMB (2 * NSTAGE * STG * 4) // 110592 B

// ---------------- device scratch ----------------
__device__ int   d_cnt[ENUM];
__device__ int   d_tok[ENUM][NTOK];
__device__ float d_gate[ENUM][NTOK];
__device__ int   d_eslot[NTOK][2];
__device__ float d_hid [ENUM*NTOK*HDIM];    // tf32-rounded hidden
__device__ float d_pair[ENUM*NTOK*CDIM];    // gate-scaled expert out
__device__ float d_sh  [NTOK*HSDIM];        // tf32-rounded shared hidden
__device__ float d_xr  [NTOK*CDIM];         // tf32-rounded x
__device__ float d_guT [ENUM*2*HDIM*CDIM];  // [E][2H][C] transposed+rounded
__device__ float d_dwT [ENUM*CDIM*HDIM];    // [E][C][H] transposed+rounded
__device__ float d_sgwr[HSDIM*CDIM];
__device__ float d_suwr[HSDIM*CDIM];
__device__ float d_sdwr[CDIM*HSDIM];

// ---------------- helpers ----------------
__device__ __forceinline__ float tf32r(float f) {
    uint32_t u; asm("cvt.rna.tf32.f32 %0, %1;" : "=r"(u) : "f"(f));
    return __uint_as_float(u);
}
__device__ __forceinline__ void cp16(float* s, const float* g) {
    uint32_t sa = (uint32_t)__cvta_generic_to_shared(s);
    asm volatile("cp.async.cg.shared.global [%0], [%1], 16;" :: "r"(sa), "l"(g));
}
__device__ __forceinline__ void mma8(float* d, const uint32_t* a, const uint32_t* b) {
    asm volatile(
        "mma.sync.aligned.m16n8k8.row.col.f32.tf32.tf32.f32 "
        "{%0,%1,%2,%3},{%4,%5,%6,%7},{%8,%9},{%0,%1,%2,%3};"
        : "+f"(d[0]), "+f"(d[1]), "+f"(d[2]), "+f"(d[3])
        : "r"(a[0]), "r"(a[1]), "r"(a[2]), "r"(a[3]), "r"(b[0]), "r"(b[1]));
}
__device__ __forceinline__ float silu_f(float v) { return v / (1.f + expf(-v)); }

// ---------------- router ----------------
__global__ void router_kernel(const float* __restrict__ x, const float* __restrict__ rw) {
    int t = blockIdx.x * (blockDim.x >> 5) + (threadIdx.x >> 5);
    int lane = threadIdx.x & 31;
    if (t >= NTOK) return;
    const float* xr = x + (long long)t * CDIM;
    float acc[ENUM];
#pragma unroll
    for (int e = 0; e < ENUM; e++) acc[e] = 0.f;
    for (int i = lane; i < CDIM; i += 32) {
        float xv = xr[i];
#pragma unroll
        for (int e = 0; e < ENUM; e++) acc[e] += xv * rw[e * CDIM + i];
    }
#pragma unroll
    for (int e = 0; e < ENUM; e++)
#pragma unroll
        for (int off = 16; off; off >>= 1) acc[e] += __shfl_xor_sync(~0u, acc[e], off);
    if (lane == 0) {
        int i0 = 0; float v0 = acc[0];
#pragma unroll
        for (int e = 1; e < ENUM; e++) if (acc[e] > v0) { v0 = acc[e]; i0 = e; }
        int i1 = -1; float v1 = -3.0e38f;
#pragma unroll
        for (int e = 0; e < ENUM; e++) if (e != i0 && acc[e] > v1) { v1 = acc[e]; i1 = e; }
        float g0 = 1.f / (1.f + expf(-v0));
        float g1 = 1.f / (1.f + expf(-v1));
        int s0 = atomicAdd(&d_cnt[i0], 1);
        int s1 = atomicAdd(&d_cnt[i1], 1);
        d_tok[i0][s0] = t; d_gate[i0][s0] = g0; d_eslot[t][0] = i0 * NTOK + s0;
        d_tok[i1][s1] = t; d_gate[i1][s1] = g1; d_eslot[t][1] = i1 * NTOK + s1;
    }
}

// ---------------- preprocessing: tf32-RNA round copy / transpose ----------------
__global__ void round_copy(const float* __restrict__ src, float* __restrict__ dst) {
    long long i = (long long)blockIdx.x * 256 + threadIdx.x;
    float4 v = ((const float4*)src)[i];
    v.x = tf32r(v.x); v.y = tf32r(v.y); v.z = tf32r(v.z); v.w = tf32r(v.w);
    ((float4*)dst)[i] = v;
}
// dst[z][c][r] = rna(src[z][r][c])
__global__ void transpose_rna(const float* __restrict__ src, float* __restrict__ dst, int R, int C) {
    __shared__ float tile[32][33];
    long long zo = (long long)blockIdx.z * R * C;
    int r0 = blockIdx.y * 32, c0 = blockIdx.x * 32;
    int tx = threadIdx.x, ty = threadIdx.y;
#pragma unroll
    for (int i = 0; i < 32; i += 8)
        tile[ty + i][tx] = src[zo + (long long)(r0 + ty + i) * C + c0 + tx];
    __syncthreads();
#pragma unroll
    for (int i = 0; i < 32; i += 8)
        dst[zo + (long long)(c0 + ty + i) * R + r0 + tx] = tf32r(tile[tx][ty + i]);
}

// ---------------- TF32 mma.sync GEMM, all operands pre-rounded (no inner cvt) ---
// A [M,K] row-major (optionally gathered rows); B K-major [N,K].
// FUSE: B smem holds 64 gate rows (B1) + 64 up rows (B2); out = rna(silu(g)*u), N_out=64
// else: B smem 128 rows of B1; N_out=128; GATE scales rows by d_gate[z][row]
template <bool GATHER, bool FUSE, bool GATE>
__global__ __launch_bounds__(256, 2) void gemm_mm(
    const float* __restrict__ Abase, long long aZ, int lda,
    const float* __restrict__ B1base, const float* __restrict__ B2base, long long bZ,
    float* __restrict__ Cbase, long long cZ, int ldc,
    int K, int useCnt)
{
    const int z = blockIdx.z, bm = blockIdx.y, bn = blockIdx.x;
    const int M = useCnt ? d_cnt[z] : NTOK;
    if (bm * BM >= M) return;

    const float* A  = Abase  + (long long)z * aZ;
    const float* B1 = B1base + (long long)z * bZ;
    const float* B2 = FUSE ? (B2base + (long long)z * bZ) : nullptr;
    float*       Cp = Cbase  + (long long)z * cZ;
    const int bnCols = FUSE ? 64 : 128;   // output cols per CTA

    extern __shared__ __align__(16) float smem[];
    float* sA = smem;
    float* sB = smem + NSTAGE * STG;

    const int tid = threadIdx.x, lane = tid & 31, w = tid >> 5;
    const int ly = lane >> 2, lx = lane & 3;

    // per-thread fixed source rows for the 4 A-chunks and 4 B-chunks
    const float* aPtr[4];
    const float* bPtr[4];
#pragma unroll
    for (int c = 0; c < 4; c++) {
        int id = c * 256 + tid;
        int row = id >> 3;
        long long arow = GATHER ? (long long)d_tok[z][bm * BM + row] : (long long)(bm * BM + row);
        aPtr[c] = A + arow * lda;
        if (FUSE) {
            int br = bn * 64 + (row & 63);
            bPtr[c] = (row < 64) ? (B1 + (long long)br * K) : (B2 + (long long)br * K);
        } else {
            bPtr[c] = B1 + (long long)(bn * 128 + row) * K;
        }
    }

    auto loadStage = [&](int st, int k0) {
        float* dA = sA + st * STG;
        float* dB = sB + st * STG;
#pragma unroll
        for (int c = 0; c < 4; c++) {
            int id = c * 256 + tid;
            int row = id >> 3, kc = (id & 7) * 4;
            cp16(dA + row * AST + kc, aPtr[c] + k0 + kc);
            cp16(dB + row * AST + kc, bPtr[c] + k0 + kc);
        }
        asm volatile("cp.async.commit_group;");
    };

    // accumulators
    float acc[4][4][4];   // non-fused: [im 0..3][in 0..3]; fused: g = acc[0..1], u = acc[2..3]
#pragma unroll
    for (int a = 0; a < 4; a++)
#pragma unroll
        for (int b = 0; b < 4; b++)
#pragma unroll
            for (int q = 0; q < 4; q++) acc[a][b][q] = 0.f;

    // warp layout
    const int wm = FUSE ? (w >> 1) : (w >> 2);   // fused: 4x2, else 2x4
    const int wn = FUSE ? (w & 1)  : (w & 3);

    const int nk = K / BK;
    loadStage(0, 0);
    loadStage(1, BK);

    for (int kt = 0; kt < nk; kt++) {
        const int st = kt % NSTAGE;
        if (kt + 1 < nk) { asm volatile("cp.async.wait_group 1;"); }
        else             { asm volatile("cp.async.wait_group 0;"); }
        __syncthreads();
        if (kt + 2 < nk) loadStage((kt + 2) % NSTAGE, (kt + 2) * BK);

        const float* cA = sA + st * STG;
        const float* cB = sB + st * STG;

#pragma unroll
        for (int ks = 0; ks < 4; ks++) {
            const int kb = ks * 8;
            if (FUSE) {
                uint32_t af[2][4], bg[4][2], bu[4][2];
#pragma unroll
                for (int im = 0; im < 2; im++) {
                    int r = wm * 32 + im * 16;
                    af[im][0] = __float_as_uint(cA[(r     + ly) * AST + kb     + lx]);
                    af[im][1] = __float_as_uint(cA[(r + 8 + ly) * AST + kb     + lx]);
                    af[im][2] = __float_as_uint(cA[(r     + ly) * AST + kb + 4 + lx]);
                    af[im][3] = __float_as_uint(cA[(r + 8 + ly) * AST + kb + 4 + lx]);
                }
#pragma unroll
                for (int in = 0; in < 4; in++) {
                    int cn = wn * 32 + in * 8 + ly;
                    bg[in][0] = __float_as_uint(cB[cn * AST + kb     + lx]);
                    bg[in][1] = __float_as_uint(cB[cn * AST + kb + 4 + lx]);
                    bu[in][0] = __float_as_uint(cB[(64 + cn) * AST + kb     + lx]);
                    bu[in][1] = __float_as_uint(cB[(64 + cn) * AST + kb + 4 + lx]);
                }
#pragma unroll
                for (int im = 0; im < 2; im++)
#pragma unroll
                    for (int in = 0; in < 4; in++) {
                        mma8(acc[im][in],     af[im], bg[in]);
                        mma8(acc[2 + im][in], af[im], bu[in]);
                    }
            } else {
                uint32_t af[4][4], bf[4][2];
#pragma unroll
                for (int im = 0; im < 4; im++) {
                    int r = wm * 64 + im * 16;
                    af[im][0] = __float_as_uint(cA[(r     + ly) * AST + kb     + lx]);
                    af[im][1] = __float_as_uint(cA[(r + 8 + ly) * AST + kb     + lx]);
                    af[im][2] = __float_as_uint(cA[(r     + ly) * AST + kb + 4 + lx]);
                    af[im][3] = __float_as_uint(cA[(r + 8 + ly) * AST + kb + 4 + lx]);
                }
#pragma unroll
                for (int in = 0; in < 4; in++) {
                    int cn = wn * 32 + in * 8 + ly;
                    bf[in][0] = __float_as_uint(cB[cn * AST + kb     + lx]);
                    bf[in][1] = __float_as_uint(cB[cn * AST + kb + 4 + lx]);
                }
#pragma unroll
                for (int im = 0; im < 4; im++)
#pragma unroll
                    for (int in = 0; in < 4; in++)
                        mma8(acc[im][in], af[im], bf[in]);
            }
        }
    }

    // ---------------- epilogue ----------------
    if (FUSE) {
#pragma unroll
        for (int im = 0; im < 2; im++) {
            int r0 = bm * BM + wm * 32 + im * 16 + ly;
#pragma unroll
            for (int in = 0; in < 4; in++) {
                int c0 = bn * 64 + wn * 32 + in * 8 + lx * 2;
                float* g = acc[im][in];
                float* u = acc[2 + im][in];
                Cp[(long long)r0 * ldc + c0]           = tf32r(silu_f(g[0]) * u[0]);
                Cp[(long long)r0 * ldc + c0 + 1]       = tf32r(silu_f(g[1]) * u[1]);
                Cp[(long long)(r0 + 8) * ldc + c0]     = tf32r(silu_f(g[2]) * u[2]);
                Cp[(long long)(r0 + 8) * ldc + c0 + 1] = tf32r(silu_f(g[3]) * u[3]);
            }
        }
    } else {
#pragma unroll
        for (int im = 0; im < 4; im++) {
            int r0 = bm * BM + wm * 64 + im * 16 + ly;
            float s0 = 1.f, s1 = 1.f;
            if (GATE) { s0 = d_gate[z][r0]; s1 = d_gate[z][r0 + 8]; }
#pragma unroll
            for (int in = 0; in < 4; in++) {
                int c0 = bn * 128 + wn * 32 + in * 8 + lx * 2;
                Cp[(long long)r0 * ldc + c0]           = acc[im][in][0] * s0;
                Cp[(long long)r0 * ldc + c0 + 1]       = acc[im][in][1] * s0;
                Cp[(long long)(r0 + 8) * ldc + c0]     = acc[im][in][2] * s1;
                Cp[(long long)(r0 + 8) * ldc + c0 + 1] = acc[im][in][3] * s1;
            }
        }
    }
    (void)bnCols;
}

// ---------------- final combine: out = shared_down_out + gated expert pair ------
__global__ void combine_kernel(float* __restrict__ out) {
    long long i = (long long)blockIdx.x * 256 + threadIdx.x;
    int t = (int)(i >> 8), j = (int)(i & 255);
    int es0 = d_eslot[t][0], es1 = d_eslot[t][1];
    float4 o  = ((float4*)out)[i];
    float4 p0 = ((const float4*)d_pair)[(long long)es0 * 256 + j];
    float4 p1 = ((const float4*)d_pair)[(long long)es1 * 256 + j];
    o.x += p0.x + p1.x; o.y += p0.y + p1.y;
    o.z += p0.z + p1.z; o.w += p0.w + p1.w;
    ((float4*)out)[i] = o;
}

// ---------------- launch ----------------
extern "C" void kernel_launch(void* const* d_in, const int* in_sizes, int n_in,
                              void* d_out, int out_size) {
    const float* x   = (const float*)d_in[0];
    const float* rw  = (const float*)d_in[1];
    const float* guw = (const float*)d_in[2];
    const float* dw  = (const float*)d_in[3];
    const float* sgw = (const float*)d_in[4];
    const float* suw = (const float*)d_in[5];
    const float* sdw = (const float*)d_in[6];
    float* out = (float*)d_out;

    void* a;
    float *p_hid, *p_pair, *p_sh, *p_xr, *p_guT, *p_dwT, *p_sgwr, *p_suwr, *p_sdwr;
    cudaGetSymbolAddress(&a, d_hid);  p_hid  = (float*)a;
    cudaGetSymbolAddress(&a, d_pair); p_pair = (float*)a;
    cudaGetSymbolAddress(&a, d_sh);   p_sh   = (float*)a;
    cudaGetSymbolAddress(&a, d_xr);   p_xr   = (float*)a;
    cudaGetSymbolAddress(&a, d_guT);  p_guT  = (float*)a;
    cudaGetSymbolAddress(&a, d_dwT);  p_dwT  = (float*)a;
    cudaGetSymbolAddress(&a, d_sgwr); p_sgwr = (float*)a;
    cudaGetSymbolAddress(&a, d_suwr); p_suwr = (float*)a;
    cudaGetSymbolAddress(&a, d_sdwr); p_sdwr = (float*)a;
    void* cntAddr; cudaGetSymbolAddress(&cntAddr, d_cnt);
    cudaMemsetAsync(cntAddr, 0, sizeof(int) * ENUM);

    cudaFuncSetAttribute(gemm_mm<true,  true,  false>, cudaFuncAttributeMaxDynamicSharedMemorySize, SMEMB);
    cudaFuncSetAttribute(gemm_mm<false, true,  false>, cudaFuncAttributeMaxDynamicSharedMemorySize, SMEMB);
    cudaFuncSetAttribute(gemm_mm<false, false, true >, cudaFuncAttributeMaxDynamicSharedMemorySize, SMEMB);
    cudaFuncSetAttribute(gemm_mm<false, false, false>, cudaFuncAttributeMaxDynamicSharedMemorySize, SMEMB);

    // router (raw x) + operand preprocessing (tf32-RNA)
    router_kernel<<<NTOK / 8, 256>>>(x, rw);
    round_copy<<<NTOK * CDIM / 1024, 256>>>(x, p_xr);
    round_copy<<<HSDIM * CDIM / 1024, 256>>>(sgw, p_sgwr);
    round_copy<<<HSDIM * CDIM / 1024, 256>>>(suw, p_suwr);
    round_copy<<<CDIM * HSDIM / 1024, 256>>>(sdw, p_sdwr);
    transpose_rna<<<dim3(32, 32, 8), dim3(32, 8)>>>(guw, p_guT, CDIM, 2 * HDIM); // [C,2H]->[2H,C]
    transpose_rna<<<dim3(32, 16, 8), dim3(32, 8)>>>(dw, p_dwT, HDIM, CDIM);      // [H,C]->[C,H]

    // expert gate_up fused SwiGLU: hid[e,slot,:] = rna(silu(x@Wg)*(x@Wu))
    gemm_mm<true, true, false><<<dim3(HDIM / 64, 32, 8), 256, SMEMB>>>(
        p_xr, 0, CDIM,
        p_guT, p_guT + (long long)HDIM * CDIM, (long long)2 * HDIM * CDIM,
        p_hid, (long long)NTOK * HDIM, HDIM,
        CDIM, 1);

    // expert down (gate-scaled): pair[e,slot,:] = gate * (hid @ dwT^T)
    gemm_mm<false, false, true><<<dim3(CDIM / 128, 32, 8), 256, SMEMB>>>(
        p_hid, (long long)NTOK * HDIM, HDIM,
        p_dwT, nullptr, (long long)CDIM * HDIM,
        p_pair, (long long)NTOK * CDIM, CDIM,
        HDIM, 1);

    // shared gate/up fused SwiGLU: sh = rna(silu(x@sgw^T)*(x@suw^T))
    gemm_mm<false, true, false><<<dim3(HSDIM / 64, 32, 1), 256, SMEMB>>>(
        p_xr, 0, CDIM,
        p_sgwr, p_suwr, 0,
        p_sh, 0, HSDIM,
        CDIM, 0);

    // shared down -> out
    gemm_mm<false, false, false><<<dim3(CDIM / 128, 32, 1), 256, SMEMB>>>(
        p_sh, 0, HSDIM,
        p_sdwr, nullptr, 0,
        out, 0, CDIM,
        HSDIM, 0);

    // out += gated expert pair
    combine_kernel<<<NTOK, 256>>>(out);

    (void)in_sizes; (void)n_in; (void)out_size;
}